// round 2
// baseline (speedup 1.0000x reference)
#include <cuda_runtime.h>
#include <math.h>

#define H_DIM 4096
#define E_DIM 64
#define TOPK  8
#define BM 64
#define BN 64
#define BK 16

// ---------------------------------------------------------------------------
// Kernel 1: router logits GEMM.  C[T,64] = A[T,4096] @ W[64,4096]^T
// 64x64 CTA tile, 256 threads, 4x4 microtile per thread, BK=16 K-chunks.
// ---------------------------------------------------------------------------
__global__ __launch_bounds__(256) void router_gemm_kernel(
    const float* __restrict__ A, const float* __restrict__ W,
    float* __restrict__ logits)
{
    __shared__ float As[BK][BM + 4];   // +4 pad keeps float4 LDS 16B-aligned,
    __shared__ float Bs[BK][BN + 4];   // row stride 272B (16B multiple)

    const int m0  = blockIdx.x * BM;
    const int tid = threadIdx.x;       // 0..255
    const int tx  = tid & 15;          // expert micro-col 0..15
    const int ty  = tid >> 4;          // token  micro-row 0..15
    const int lr  = tid >> 2;          // load row 0..63
    const int lc  = (tid & 3) << 2;    // load col {0,4,8,12}

    const float* aptr = A + (size_t)(m0 + lr) * H_DIM + lc;
    const float* bptr = W + (size_t)lr * H_DIM + lc;

    float acc[4][4] = {};

    for (int k0 = 0; k0 < H_DIM; k0 += BK) {
        float4 av = *reinterpret_cast<const float4*>(aptr + k0);
        float4 bv = *reinterpret_cast<const float4*>(bptr + k0);
        As[lc + 0][lr] = av.x; As[lc + 1][lr] = av.y;
        As[lc + 2][lr] = av.z; As[lc + 3][lr] = av.w;
        Bs[lc + 0][lr] = bv.x; Bs[lc + 1][lr] = bv.y;
        Bs[lc + 2][lr] = bv.z; Bs[lc + 3][lr] = bv.w;
        __syncthreads();

        #pragma unroll
        for (int k = 0; k < BK; k++) {
            float4 a4 = *reinterpret_cast<const float4*>(&As[k][ty << 2]);
            float4 b4 = *reinterpret_cast<const float4*>(&Bs[k][tx << 2]);
            float ar[4] = {a4.x, a4.y, a4.z, a4.w};
            float br[4] = {b4.x, b4.y, b4.z, b4.w};
            #pragma unroll
            for (int i = 0; i < 4; i++)
                #pragma unroll
                for (int j = 0; j < 4; j++)
                    acc[i][j] = fmaf(ar[i], br[j], acc[i][j]);
        }
        __syncthreads();
    }

    #pragma unroll
    for (int i = 0; i < 4; i++) {
        const int m = m0 + (ty << 2) + i;
        float4 o = make_float4(acc[i][0], acc[i][1], acc[i][2], acc[i][3]);
        *reinterpret_cast<float4*>(&logits[(size_t)m * E_DIM + (tx << 2)]) = o;
    }
}

// ---------------------------------------------------------------------------
// Kernel 2: top-8 + renormalized softmax scores, one warp per token.
// softmax is monotone => top-k of softmax == top-k of logits, and
// score_i = exp(l_i - m) / sum_top8 exp(l_j - m)  (global Z cancels).
// Argmax tiebreak prefers the lower index, matching jax.lax.top_k stability.
// ---------------------------------------------------------------------------
__global__ __launch_bounds__(256) void topk_kernel(
    const float* __restrict__ logits,
    float* __restrict__ scores,
    float* __restrict__ indices, int T)
{
    const int warp = (int)((blockIdx.x * blockDim.x + threadIdx.x) >> 5);
    const int lane = threadIdx.x & 31;
    if (warp >= T) return;

    const float* lg = logits + (size_t)warp * E_DIM;
    float v0 = lg[lane];
    float v1 = lg[lane + 32];

    float topv[TOPK];
    int   topi[TOPK];

    #pragma unroll
    for (int r = 0; r < TOPK; r++) {
        bool p   = (v0 >= v1);           // tie -> lower index (lane < lane+32)
        float lv = p ? v0 : v1;
        int   li = p ? lane : lane + 32;
        #pragma unroll
        for (int off = 16; off > 0; off >>= 1) {
            float ov = __shfl_xor_sync(0xffffffffu, lv, off);
            int   oi = __shfl_xor_sync(0xffffffffu, li, off);
            if (ov > lv || (ov == lv && oi < li)) { lv = ov; li = oi; }
        }
        topv[r] = lv; topi[r] = li;
        if (li == lane)           v0 = -INFINITY;
        else if (li == lane + 32) v1 = -INFINITY;
    }

    if (lane == 0) {
        const float m = topv[0];
        float e[TOPK], s = 0.f;
        #pragma unroll
        for (int r = 0; r < TOPK; r++) { e[r] = expf(topv[r] - m); s += e[r]; }
        const float inv = 1.f / s;
        #pragma unroll
        for (int r = 0; r < TOPK; r++) {
            scores [(size_t)warp * TOPK + r] = e[r] * inv;
            indices[(size_t)warp * TOPK + r] = (float)topi[r];
        }
    }
}

// ---------------------------------------------------------------------------
extern "C" void kernel_launch(void* const* d_in, const int* in_sizes, int n_in,
                              void* d_out, int out_size)
{
    const float* hs = (const float*)d_in[0];   // hidden_states [T, 4096]
    const float* w  = (const float*)d_in[1];   // weight        [64, 4096]
    const int T = in_sizes[0] / H_DIM;

    float* out     = (float*)d_out;
    float* logits  = out;                                  // T*64
    float* scores  = out + (size_t)T * E_DIM;              // T*8
    float* indices = scores + (size_t)T * TOPK;            // T*8 (as floats)

    router_gemm_kernel<<<T / BM, 256>>>(hs, w, logits);

    const int warps_per_block = 256 / 32;
    const int grid = (T + warps_per_block - 1) / warps_per_block;
    topk_kernel<<<grid, 256>>>(logits, scores, indices, T);
}

// round 6
// speedup vs baseline: 1.0119x; 1.0119x over previous
#include <cuda_runtime.h>
#include <cuda_bf16.h>
#include <math.h>
#include <stdint.h>

#define H_DIM 4096
#define E_DIM 64
#define TOPK  8
#define BM 64
#define BN 64
#define BK 16

typedef unsigned long long u64;

// Two independent RN fp32 FMAs in one instruction (Blackwell packed-f32 pipe).
// Each half is a normal IEEE RN fmaf -> per-output accumulation chain is
// identical (in op count, order, and rounding mode) to the verified R1 kernel.
__device__ __forceinline__ void fma2(u64& d, u64 a, u64 b) {
    asm("fma.rn.f32x2 %0, %1, %2, %0;" : "+l"(d) : "l"(a), "l"(b));
}
__device__ __forceinline__ u64 pk2(float x) {   // (x, x)
    u64 r;
    asm("mov.b64 %0, {%1, %1};" : "=l"(r) : "f"(x));
    return r;
}
__device__ __forceinline__ void upk(u64 v, float& lo, float& hi) {
    asm("mov.b64 {%0, %1}, %2;" : "=f"(lo), "=f"(hi) : "l"(v));
}

// ---------------------------------------------------------------------------
// Kernel 1: router logits GEMM.  C[T,64] = A[T,4096] @ W[64,4096]^T
// Identical structure/layout/order to the R1 (passing) kernel; the 4x4
// microtile now packs expert pairs into f32x2 FMAs.
// ---------------------------------------------------------------------------
__global__ __launch_bounds__(256) void router_gemm_kernel(
    const float* __restrict__ A, const float* __restrict__ W,
    float* __restrict__ logits)
{
    __shared__ float As[BK][BM + 4];
    __shared__ float Bs[BK][BN + 4];

    const int m0  = blockIdx.x * BM;
    const int tid = threadIdx.x;       // 0..255
    const int tx  = tid & 15;          // expert micro-col 0..15
    const int ty  = tid >> 4;          // token  micro-row 0..15
    const int lr  = tid >> 2;          // load row 0..63
    const int lc  = (tid & 3) << 2;    // load col {0,4,8,12}

    const float* aptr = A + (size_t)(m0 + lr) * H_DIM + lc;
    const float* bptr = W + (size_t)lr * H_DIM + lc;

    u64 acc2[4][2];
    #pragma unroll
    for (int i = 0; i < 4; i++) { acc2[i][0] = 0ull; acc2[i][1] = 0ull; }

    for (int k0 = 0; k0 < H_DIM; k0 += BK) {
        float4 av = *reinterpret_cast<const float4*>(aptr + k0);
        float4 bv = *reinterpret_cast<const float4*>(bptr + k0);
        As[lc + 0][lr] = av.x; As[lc + 1][lr] = av.y;
        As[lc + 2][lr] = av.z; As[lc + 3][lr] = av.w;
        Bs[lc + 0][lr] = bv.x; Bs[lc + 1][lr] = bv.y;
        Bs[lc + 2][lr] = bv.z; Bs[lc + 3][lr] = bv.w;
        __syncthreads();

        #pragma unroll
        for (int k = 0; k < BK; k++) {
            float4 a4 = *reinterpret_cast<const float4*>(&As[k][ty << 2]);
            const u64* bp = reinterpret_cast<const u64*>(&Bs[k][tx << 2]);
            u64 b0 = bp[0], b1 = bp[1];          // expert pairs (c,c+1),(c+2,c+3)
            u64 a0 = pk2(a4.x), a1 = pk2(a4.y), a2 = pk2(a4.z), a3 = pk2(a4.w);
            fma2(acc2[0][0], a0, b0); fma2(acc2[0][1], a0, b1);
            fma2(acc2[1][0], a1, b0); fma2(acc2[1][1], a1, b1);
            fma2(acc2[2][0], a2, b0); fma2(acc2[2][1], a2, b1);
            fma2(acc2[3][0], a3, b0); fma2(acc2[3][1], a3, b1);
        }
        __syncthreads();
    }

    #pragma unroll
    for (int i = 0; i < 4; i++) {
        const int m = m0 + (ty << 2) + i;
        float4 o;
        upk(acc2[i][0], o.x, o.y);
        upk(acc2[i][1], o.z, o.w);
        *reinterpret_cast<float4*>(&logits[(size_t)m * E_DIM + (tx << 2)]) = o;
    }
}

// ---------------------------------------------------------------------------
// Kernel 2: top-8 + renormalized softmax scores (unchanged, verified in R1)
// ---------------------------------------------------------------------------
__global__ __launch_bounds__(256) void topk_kernel(
    const float* __restrict__ logits,
    float* __restrict__ scores,
    float* __restrict__ indices, int T)
{
    const int warp = (int)((blockIdx.x * blockDim.x + threadIdx.x) >> 5);
    const int lane = threadIdx.x & 31;
    if (warp >= T) return;

    const float* lg = logits + (size_t)warp * E_DIM;
    float v0 = lg[lane];
    float v1 = lg[lane + 32];

    float topv[TOPK];
    int   topi[TOPK];

    #pragma unroll
    for (int r = 0; r < TOPK; r++) {
        bool p   = (v0 >= v1);           // tie -> lower index
        float lv = p ? v0 : v1;
        int   li = p ? lane : lane + 32;
        #pragma unroll
        for (int off = 16; off > 0; off >>= 1) {
            float ov = __shfl_xor_sync(0xffffffffu, lv, off);
            int   oi = __shfl_xor_sync(0xffffffffu, li, off);
            if (ov > lv || (ov == lv && oi < li)) { lv = ov; li = oi; }
        }
        topv[r] = lv; topi[r] = li;
        if (li == lane)           v0 = -INFINITY;
        else if (li == lane + 32) v1 = -INFINITY;
    }

    if (lane == 0) {
        const float m = topv[0];
        float e[TOPK], s = 0.f;
        #pragma unroll
        for (int r = 0; r < TOPK; r++) { e[r] = expf(topv[r] - m); s += e[r]; }
        const float inv = 1.f / s;
        #pragma unroll
        for (int r = 0; r < TOPK; r++) {
            scores [(size_t)warp * TOPK + r] = e[r] * inv;
            indices[(size_t)warp * TOPK + r] = (float)topi[r];
        }
    }
}

// ---------------------------------------------------------------------------
extern "C" void kernel_launch(void* const* d_in, const int* in_sizes, int n_in,
                              void* d_out, int out_size)
{
    const float* hs = (const float*)d_in[0];   // hidden_states [T, 4096]
    const float* w  = (const float*)d_in[1];   // weight        [64, 4096]
    const int T = in_sizes[0] / H_DIM;

    float* out     = (float*)d_out;
    float* logits  = out;                                  // T*64
    float* scores  = out + (size_t)T * E_DIM;              // T*8
    float* indices = scores + (size_t)T * TOPK;            // T*8 (as floats)

    router_gemm_kernel<<<T / BM, 256>>>(hs, w, logits);

    const int warps_per_block = 256 / 32;
    const int grid = (T + warps_per_block - 1) / warps_per_block;
    topk_kernel<<<grid, 256>>>(logits, scores, indices, T);
}